// round 2
// baseline (speedup 1.0000x reference)
#include <cuda_runtime.h>
#include <cstdint>

#define BB 4096
#define TT 512
#define IND 5
#define E 30
#define NH 3
#define HD 10
#define KSPLIT 8
#define KTILE 512   // 4096 / KSPLIT
#define RQ 4        // q rows per thread in attention

typedef unsigned long long u64;

// ---------------- scratch (device globals; no allocations allowed) ----------
__device__ float g_hn[BB * E];
__device__ float g_cn[BB * E];
__device__ float g_q[BB * E];
__device__ float g_k[BB * E];
__device__ float g_v[BB * E];
__device__ float g_psum[NH * KSPLIT * BB];
__device__ float g_pacc[NH * KSPLIT * BB * HD];

// ---------------- f32x2 helpers ----------------------------------------------
__device__ __forceinline__ u64 pack2(float lo, float hi) {
    u64 r; asm("mov.b64 %0, {%1, %2};" : "=l"(r) : "f"(lo), "f"(hi)); return r;
}
__device__ __forceinline__ u64 bcast2(float v) {
    u64 r; asm("mov.b64 %0, {%1, %1};" : "=l"(r) : "f"(v)); return r;
}
__device__ __forceinline__ void unpack2(u64 p, float& lo, float& hi) {
    asm("mov.b64 {%0, %1}, %2;" : "=f"(lo), "=f"(hi) : "l"(p));
}
__device__ __forceinline__ u64 ffma2(u64 a, u64 b, u64 c) {
    u64 d; asm("fma.rn.f32x2 %0, %1, %2, %3;" : "=l"(d) : "l"(a), "l"(b), "l"(c));
    return d;
}

// ---------------- activation helpers -----------------------------------------
__device__ __forceinline__ float fsigmoid(float x) {
    return __fdividef(1.0f, 1.0f + __expf(-x));
}
__device__ __forceinline__ float ftanh(float x) {
    return __fdividef(2.0f, 1.0f + __expf(-2.0f * x)) - 1.0f;
}
__device__ __forceinline__ float warp_sum(float v) {
    #pragma unroll
    for (int o = 16; o > 0; o >>= 1) v += __shfl_xor_sync(0xffffffffu, v, o);
    return v;
}

// ---------------- kernel 1: LSTM, f32x2-packed gates --------------------------
__global__ __launch_bounds__(128, 2) void lstm_kernel(
    const float* __restrict__ input, const float* __restrict__ w_ih,
    const float* __restrict__ w_hh, const float* __restrict__ b_ih,
    const float* __restrict__ b_hh)
{
    int warp = (blockIdx.x * blockDim.x + threadIdx.x) >> 5;
    int lane = threadIdx.x & 31;
    bool act = lane < E;
    int li = act ? lane : 0;

    // packed weights: lane li owns gate rows (li, E+li) -> IF, (2E+li, 3E+li) -> GO
    u64 wihIF[IND], wihGO[IND];
    #pragma unroll
    for (int k = 0; k < IND; k++) {
        wihIF[k] = pack2(__ldg(w_ih + (0 * E + li) * IND + k),
                         __ldg(w_ih + (1 * E + li) * IND + k));
        wihGO[k] = pack2(__ldg(w_ih + (2 * E + li) * IND + k),
                         __ldg(w_ih + (3 * E + li) * IND + k));
    }
    u64 whhIF[E], whhGO[E];
    #pragma unroll
    for (int j = 0; j < E; j++) {
        whhIF[j] = pack2(__ldg(w_hh + (0 * E + li) * E + j),
                         __ldg(w_hh + (1 * E + li) * E + j));
        whhGO[j] = pack2(__ldg(w_hh + (2 * E + li) * E + j),
                         __ldg(w_hh + (3 * E + li) * E + j));
    }
    u64 bIF = pack2(__ldg(b_ih + 0 * E + li) + __ldg(b_hh + 0 * E + li),
                    __ldg(b_ih + 1 * E + li) + __ldg(b_hh + 1 * E + li));
    u64 bGO = pack2(__ldg(b_ih + 2 * E + li) + __ldg(b_hh + 2 * E + li),
                    __ldg(b_ih + 3 * E + li) + __ldg(b_hh + 3 * E + li));

    const float* xp = input + (size_t)warp * TT * IND;
    float h = 0.0f, c = 0.0f;

    auto step = [&](const float* xv) {
        u64 aIF = bIF, aGO = bGO;
        #pragma unroll
        for (int k = 0; k < IND; k++) {
            u64 x2 = bcast2(xv[k]);
            aIF = ffma2(wihIF[k], x2, aIF);
            aGO = ffma2(wihGO[k], x2, aGO);
        }
        #pragma unroll
        for (int j = 0; j < E; j++) {
            float hj = __shfl_sync(0xffffffffu, h, j);
            u64 h2 = bcast2(hj);
            aIF = ffma2(whhIF[j], h2, aIF);
            aGO = ffma2(whhGO[j], h2, aGO);
        }
        float ai, af, ag, ao;
        unpack2(aIF, ai, af);
        unpack2(aGO, ag, ao);
        float ig = fsigmoid(ai);
        float fg = fsigmoid(af);
        float gg = ftanh(ag);
        float og = fsigmoid(ao);
        c = fmaf(fg, c, ig * gg);
        h = og * ftanh(c);
    };

    float xA[IND], xB[IND];
    #pragma unroll
    for (int k = 0; k < IND; k++) xA[k] = __ldg(xp + k);

    for (int t = 0; t < TT; t += 2) {
        // prefetch x[t+1] while computing step t
        const float* p1 = xp + (t + 1) * IND;
        #pragma unroll
        for (int k = 0; k < IND; k++) xB[k] = __ldg(p1 + k);
        step(xA);
        // prefetch x[t+2] (clamped; value unused on last pair) while computing t+1
        int t2 = (t + 2 < TT) ? (t + 2) : 0;
        const float* p2 = xp + t2 * IND;
        #pragma unroll
        for (int k = 0; k < IND; k++) xA[k] = __ldg(p2 + k);
        step(xB);
    }

    if (act) {
        g_hn[(size_t)warp * E + lane] = h;
        g_cn[(size_t)warp * E + lane] = c;
    }
}

// ---------------- kernel 2: QKV projections (warp per row) --------------------
__global__ __launch_bounds__(256) void qkv_kernel(
    const float* __restrict__ ipw, const float* __restrict__ ipb)
{
    int warp = (blockIdx.x * blockDim.x + threadIdx.x) >> 5;
    int lane = threadIdx.x & 31;
    bool act = lane < E;
    int li = act ? lane : 0;

    float h = g_hn[(size_t)warp * E + li];
    float c = g_cn[(size_t)warp * E + li];
    float aq = __ldg(ipb + 0 * E + li);
    float ak = __ldg(ipb + 1 * E + li);
    float av = __ldg(ipb + 2 * E + li);
    #pragma unroll
    for (int j = 0; j < E; j++) {
        float hj = __shfl_sync(0xffffffffu, h, j);
        float cj = __shfl_sync(0xffffffffu, c, j);
        aq = fmaf(__ldg(ipw + (0 * E + li) * E + j), hj, aq);
        ak = fmaf(__ldg(ipw + (1 * E + li) * E + j), cj, ak);
        av = fmaf(__ldg(ipw + (2 * E + li) * E + j), cj, av);
    }
    if (act) {
        g_q[(size_t)warp * E + lane] = aq;
        g_k[(size_t)warp * E + lane] = ak;
        g_v[(size_t)warp * E + lane] = av;
    }
}

// ---------------- kernel 3: attention partials (flash-style, no-max) ----------
__global__ __launch_bounds__(128) void attn_kernel()
{
    __shared__ u64 ks2[KTILE * 5];
    __shared__ u64 vs2[KTILE * 5];
    int h   = blockIdx.z;
    int ksp = blockIdx.y;
    int qc  = blockIdx.x;
    int tid = threadIdx.x;
    int k0  = ksp * KTILE;

    for (int i = tid; i < KTILE * 5; i += 128) {
        int m = i / 5, p = i - m * 5;
        const float2* kp = (const float2*)(g_k + (size_t)(k0 + m) * E + h * HD) + p;
        const float2* vp = (const float2*)(g_v + (size_t)(k0 + m) * E + h * HD) + p;
        float2 kv = *kp; float2 vv = *vp;
        ks2[i] = pack2(kv.x, kv.y);
        vs2[i] = pack2(vv.x, vv.y);
    }
    __syncthreads();

    int q0 = qc * (128 * RQ) + tid * RQ;

    u64 qp[RQ][5], accp[RQ][5];
    float s[RQ];
    #pragma unroll
    for (int r = 0; r < RQ; r++) {
        s[r] = 0.0f;
        #pragma unroll
        for (int p = 0; p < 5; p++) {
            float2 t = *((const float2*)(g_q + (size_t)(q0 + r) * E + h * HD) + p);
            qp[r][p] = pack2(t.x * 0.3162277660168379f, t.y * 0.3162277660168379f);
            accp[r][p] = pack2(0.0f, 0.0f);
        }
    }

    for (int m = 0; m < KTILE; m++) {
        u64 kk[5], vv[5];
        #pragma unroll
        for (int p = 0; p < 5; p++) { kk[p] = ks2[m * 5 + p]; vv[p] = vs2[m * 5 + p]; }
        #pragma unroll
        for (int r = 0; r < RQ; r++) {
            u64 d2 = pack2(0.0f, 0.0f);
            #pragma unroll
            for (int p = 0; p < 5; p++) d2 = ffma2(qp[r][p], kk[p], d2);
            float lo, hi; unpack2(d2, lo, hi);
            float pr = __expf(lo + hi);
            s[r] += pr;
            u64 p2 = bcast2(pr);
            #pragma unroll
            for (int p = 0; p < 5; p++) accp[r][p] = ffma2(p2, vv[p], accp[r][p]);
        }
    }

    #pragma unroll
    for (int r = 0; r < RQ; r++) {
        int base = (h * KSPLIT + ksp) * BB + (q0 + r);
        g_psum[base] = s[r];
        #pragma unroll
        for (int p = 0; p < 5; p++) {
            float lo, hi; unpack2(accp[r][p], lo, hi);
            g_pacc[(size_t)base * HD + 2 * p]     = lo;
            g_pacc[(size_t)base * HD + 2 * p + 1] = hi;
        }
    }
}

// ---------------- kernel 4: combine + out_proj + LN + MLP + LN + head --------
__global__ __launch_bounds__(256) void epi_kernel(
    const float* __restrict__ opw, const float* __restrict__ opb,
    const float* __restrict__ f1w, const float* __restrict__ f1b,
    const float* __restrict__ f2w, const float* __restrict__ f2b,
    const float* __restrict__ lng, const float* __restrict__ lnb,
    const float* __restrict__ ow,  const float* __restrict__ ob,
    float* __restrict__ out)
{
    int warp = (blockIdx.x * blockDim.x + threadIdx.x) >> 5;
    int lane = threadIdx.x & 31;
    bool act = lane < E;
    int li = act ? lane : 0;
    int hh = li / HD, dd = li - hh * HD;

    // combine split-softmax partials
    float num = 0.0f, den = 0.0f;
    #pragma unroll
    for (int ksp = 0; ksp < KSPLIT; ksp++) {
        int base = (hh * KSPLIT + ksp) * BB + warp;
        num += g_pacc[(size_t)base * HD + dd];
        den += g_psum[base];
    }
    float ctx = __fdividef(num, den);

    // out_proj
    float ao = __ldg(opb + li);
    #pragma unroll
    for (int j = 0; j < E; j++) {
        float cj = __shfl_sync(0xffffffffu, ctx, j);
        ao = fmaf(__ldg(opw + li * E + j), cj, ao);
    }
    float r1 = ao + g_hn[(size_t)warp * E + li];

    // LN1
    float lg = __ldg(lng + li), lb = __ldg(lnb + li);
    float mu = warp_sum(act ? r1 : 0.0f) * (1.0f / E);
    float dv = act ? (r1 - mu) : 0.0f;
    float var = warp_sum(dv * dv) * (1.0f / E);
    float x1 = fmaf(dv * rsqrtf(var + 1e-5f), lg, lb);
    if (!act) x1 = 0.0f;

    // fc1 + exact GELU
    float y = __ldg(f1b + li);
    #pragma unroll
    for (int j = 0; j < E; j++) {
        float xj = __shfl_sync(0xffffffffu, x1, j);
        y = fmaf(__ldg(f1w + li * E + j), xj, y);
    }
    float gy = 0.5f * y * (1.0f + erff(y * 0.7071067811865475f));

    // fc2
    float z = __ldg(f2b + li);
    #pragma unroll
    for (int j = 0; j < E; j++) {
        float gj = __shfl_sync(0xffffffffu, gy, j);
        z = fmaf(__ldg(f2w + li * E + j), gj, z);
    }
    float r2 = x1 + z;

    // LN2
    float mu2 = warp_sum(act ? r2 : 0.0f) * (1.0f / E);
    float dv2 = act ? (r2 - mu2) : 0.0f;
    float var2 = warp_sum(dv2 * dv2) * (1.0f / E);
    float x2 = fmaf(dv2 * rsqrtf(var2 + 1e-5f), lg, lb);
    if (!act) x2 = 0.0f;

    // final head [E -> 3]
    float o0 = __ldg(ob + 0), o1 = __ldg(ob + 1), o2 = __ldg(ob + 2);
    #pragma unroll
    for (int j = 0; j < E; j++) {
        float xj = __shfl_sync(0xffffffffu, x2, j);
        o0 = fmaf(__ldg(ow + 0 * E + j), xj, o0);
        o1 = fmaf(__ldg(ow + 1 * E + j), xj, o1);
        o2 = fmaf(__ldg(ow + 2 * E + j), xj, o2);
    }
    if (lane == 0) {
        out[(size_t)warp * 3 + 0] = o0;
        out[(size_t)warp * 3 + 1] = o1;
        out[(size_t)warp * 3 + 2] = o2;
    }
}

// ---------------- launch ------------------------------------------------------
extern "C" void kernel_launch(void* const* d_in, const int* in_sizes, int n_in,
                              void* d_out, int out_size)
{
    const float* input = (const float*)d_in[0];   // [4096,512,5]
    const float* w_ih  = (const float*)d_in[1];   // [120,5]
    const float* w_hh  = (const float*)d_in[2];   // [120,30]
    const float* b_ih  = (const float*)d_in[3];   // [120]
    const float* b_hh  = (const float*)d_in[4];   // [120]
    const float* ipw   = (const float*)d_in[5];   // [90,30]
    const float* ipb   = (const float*)d_in[6];   // [90]
    const float* opw   = (const float*)d_in[7];   // [30,30]
    const float* opb   = (const float*)d_in[8];   // [30]
    const float* f1w   = (const float*)d_in[9];   // [30,30]
    const float* f1b   = (const float*)d_in[10];  // [30]
    const float* f2w   = (const float*)d_in[11];  // [30,30]
    const float* f2b   = (const float*)d_in[12];  // [30]
    const float* lng   = (const float*)d_in[13];  // [30]
    const float* lnb   = (const float*)d_in[14];  // [30]
    const float* ow    = (const float*)d_in[15];  // [3,30]
    const float* ob    = (const float*)d_in[16];  // [3]
    float* out = (float*)d_out;

    lstm_kernel<<<BB / 4, 128>>>(input, w_ih, w_hh, b_ih, b_hh);
    qkv_kernel<<<BB / 8, 256>>>(ipw, ipb);
    attn_kernel<<<dim3(BB / (128 * RQ), KSPLIT, NH), 128>>>();
    epi_kernel<<<BB / 8, 256>>>(opw, opb, f1w, f1b, f2w, f2b, lng, lnb, ow, ob, out);
}

// round 3
// speedup vs baseline: 1.5408x; 1.5408x over previous
#include <cuda_runtime.h>
#include <cstdint>

#define BB 4096
#define TT 512
#define IND 5
#define E 30
#define NH 3
#define HD 10
#define KSPLIT 8
#define KTILE 512   // 4096 / KSPLIT
#define RQ 4        // q rows per thread in attention

typedef unsigned long long u64;

// ---------------- scratch (device globals; no allocations allowed) ----------
__device__ float g_hn[BB * E];
__device__ float g_cn[BB * E];
__device__ float g_q[BB * E];
__device__ float g_k[BB * E];
__device__ float g_v[BB * E];
__device__ float g_psum[NH * KSPLIT * BB];
__device__ float g_pacc[NH * KSPLIT * BB * HD];

// ---------------- f32x2 helpers ----------------------------------------------
__device__ __forceinline__ u64 pack2(float lo, float hi) {
    u64 r; asm("mov.b64 %0, {%1, %2};" : "=l"(r) : "f"(lo), "f"(hi)); return r;
}
__device__ __forceinline__ u64 bcast2(float v) {
    u64 r; asm("mov.b64 %0, {%1, %1};" : "=l"(r) : "f"(v)); return r;
}
__device__ __forceinline__ void unpack2(u64 p, float& lo, float& hi) {
    asm("mov.b64 {%0, %1}, %2;" : "=f"(lo), "=f"(hi) : "l"(p));
}
__device__ __forceinline__ u64 ffma2(u64 a, u64 b, u64 c) {
    u64 d; asm("fma.rn.f32x2 %0, %1, %2, %3;" : "=l"(d) : "l"(a), "l"(b), "l"(c));
    return d;
}

// ---------------- activation helpers -----------------------------------------
__device__ __forceinline__ float fsigmoid(float x) {
    return __fdividef(1.0f, 1.0f + __expf(-x));
}
__device__ __forceinline__ float ftanh(float x) {
    return __fdividef(2.0f, 1.0f + __expf(-2.0f * x)) - 1.0f;
}
__device__ __forceinline__ float warp_sum(float v) {
    #pragma unroll
    for (int o = 16; o > 0; o >>= 1) v += __shfl_xor_sync(0xffffffffu, v, o);
    return v;
}

// ---------------- kernel 1: LSTM, j-packed f32x2, smem h pairs ----------------
// Lane li owns the 4 gate outputs (i,f,g,o) for hidden unit li. The recurrent
// dot-product runs over j in pairs: multiplier pair (h_2p, h_2p+1) comes
// straight out of a 64-bit LDS from the per-warp h staging buffer, so no
// shfl and no packing MOVs appear in the inner loop.
__global__ __launch_bounds__(128, 2) void lstm_kernel(
    const float* __restrict__ input, const float* __restrict__ w_ih,
    const float* __restrict__ w_hh, const float* __restrict__ b_ih,
    const float* __restrict__ b_hh)
{
    __shared__ __align__(16) float hbuf[4][2][32];   // [warp][double-buf][lane]

    int wl   = threadIdx.x >> 5;
    int warp = blockIdx.x * 4 + wl;
    int lane = threadIdx.x & 31;
    bool act = lane < E;
    int li = act ? lane : 0;

    // per-lane packed recurrent weights: whh2[g][p] = (W[g*E+li][2p], W[g*E+li][2p+1])
    u64 whh2[4][15];
    #pragma unroll
    for (int g = 0; g < 4; g++) {
        const float* wr = w_hh + (g * E + li) * E;
        #pragma unroll
        for (int p = 0; p < 15; p++)
            whh2[g][p] = pack2(__ldg(wr + 2 * p), __ldg(wr + 2 * p + 1));
    }
    u64 wx01[4], wx23[4];
    float wx4[4], bias[4];
    #pragma unroll
    for (int g = 0; g < 4; g++) {
        const float* wr = w_ih + (g * E + li) * IND;
        wx01[g] = pack2(__ldg(wr + 0), __ldg(wr + 1));
        wx23[g] = pack2(__ldg(wr + 2), __ldg(wr + 3));
        wx4[g]  = __ldg(wr + 4);
        bias[g] = __ldg(b_ih + g * E + li) + __ldg(b_hh + g * E + li);
    }

    const float* xp = input + (size_t)warp * TT * IND;
    float h = 0.0f, c = 0.0f;
    const u64 zero2 = pack2(0.0f, 0.0f);

    for (int t = 0; t < TT; t++) {
        // load x[t] early to hide LDG latency behind the smem stage
        float x0 = __ldg(xp + 0), x1 = __ldg(xp + 1), x2 = __ldg(xp + 2);
        float x3 = __ldg(xp + 3), x4 = __ldg(xp + 4);
        xp += IND;

        // stage h into smem (double-buffered, one syncwarp per step)
        float* hb = hbuf[wl][t & 1];
        hb[lane] = h;
        __syncwarp();
        const u64* hv = (const u64*)hb;
        u64 hp[15];
        #pragma unroll
        for (int p = 0; p < 15; p++) hp[p] = hv[p];

        u64 x01 = pack2(x0, x1), x23 = pack2(x2, x3);

        float a[4];
        #pragma unroll
        for (int g = 0; g < 4; g++) {
            u64 a2 = ffma2(wx01[g], x01, zero2);
            a2 = ffma2(wx23[g], x23, a2);
            #pragma unroll
            for (int p = 0; p < 15; p++) a2 = ffma2(whh2[g][p], hp[p], a2);
            float lo, hi; unpack2(a2, lo, hi);
            a[g] = fmaf(wx4[g], x4, bias[g]) + lo + hi;
        }

        float ig = fsigmoid(a[0]);
        float fg = fsigmoid(a[1]);
        float gg = ftanh(a[2]);
        float og = fsigmoid(a[3]);
        c = fmaf(fg, c, ig * gg);
        h = og * ftanh(c);
    }

    if (act) {
        g_hn[(size_t)warp * E + lane] = h;
        g_cn[(size_t)warp * E + lane] = c;
    }
}

// ---------------- kernel 2: QKV projections (warp per row) --------------------
__global__ __launch_bounds__(256) void qkv_kernel(
    const float* __restrict__ ipw, const float* __restrict__ ipb)
{
    int warp = (blockIdx.x * blockDim.x + threadIdx.x) >> 5;
    int lane = threadIdx.x & 31;
    bool act = lane < E;
    int li = act ? lane : 0;

    float h = g_hn[(size_t)warp * E + li];
    float c = g_cn[(size_t)warp * E + li];
    float aq = __ldg(ipb + 0 * E + li);
    float ak = __ldg(ipb + 1 * E + li);
    float av = __ldg(ipb + 2 * E + li);
    #pragma unroll
    for (int j = 0; j < E; j++) {
        float hj = __shfl_sync(0xffffffffu, h, j);
        float cj = __shfl_sync(0xffffffffu, c, j);
        aq = fmaf(__ldg(ipw + (0 * E + li) * E + j), hj, aq);
        ak = fmaf(__ldg(ipw + (1 * E + li) * E + j), cj, ak);
        av = fmaf(__ldg(ipw + (2 * E + li) * E + j), cj, av);
    }
    if (act) {
        g_q[(size_t)warp * E + lane] = aq;
        g_k[(size_t)warp * E + lane] = ak;
        g_v[(size_t)warp * E + lane] = av;
    }
}

// ---------------- kernel 3: attention partials (flash-style, no-max) ----------
__global__ __launch_bounds__(128) void attn_kernel()
{
    __shared__ u64 ks2[KTILE * 5];
    __shared__ u64 vs2[KTILE * 5];
    int h   = blockIdx.z;
    int ksp = blockIdx.y;
    int qc  = blockIdx.x;
    int tid = threadIdx.x;
    int k0  = ksp * KTILE;

    for (int i = tid; i < KTILE * 5; i += 128) {
        int m = i / 5, p = i - m * 5;
        const float2* kp = (const float2*)(g_k + (size_t)(k0 + m) * E + h * HD) + p;
        const float2* vp = (const float2*)(g_v + (size_t)(k0 + m) * E + h * HD) + p;
        float2 kv = *kp; float2 vv = *vp;
        ks2[i] = pack2(kv.x, kv.y);
        vs2[i] = pack2(vv.x, vv.y);
    }
    __syncthreads();

    int q0 = qc * (128 * RQ) + tid * RQ;

    u64 qp[RQ][5], accp[RQ][5];
    float s[RQ];
    #pragma unroll
    for (int r = 0; r < RQ; r++) {
        s[r] = 0.0f;
        #pragma unroll
        for (int p = 0; p < 5; p++) {
            float2 t = *((const float2*)(g_q + (size_t)(q0 + r) * E + h * HD) + p);
            qp[r][p] = pack2(t.x * 0.3162277660168379f, t.y * 0.3162277660168379f);
            accp[r][p] = pack2(0.0f, 0.0f);
        }
    }

    for (int m = 0; m < KTILE; m++) {
        u64 kk[5], vv[5];
        #pragma unroll
        for (int p = 0; p < 5; p++) { kk[p] = ks2[m * 5 + p]; vv[p] = vs2[m * 5 + p]; }
        #pragma unroll
        for (int r = 0; r < RQ; r++) {
            u64 d2 = pack2(0.0f, 0.0f);
            #pragma unroll
            for (int p = 0; p < 5; p++) d2 = ffma2(qp[r][p], kk[p], d2);
            float lo, hi; unpack2(d2, lo, hi);
            float pr = __expf(lo + hi);
            s[r] += pr;
            u64 p2 = bcast2(pr);
            #pragma unroll
            for (int p = 0; p < 5; p++) accp[r][p] = ffma2(p2, vv[p], accp[r][p]);
        }
    }

    #pragma unroll
    for (int r = 0; r < RQ; r++) {
        int base = (h * KSPLIT + ksp) * BB + (q0 + r);
        g_psum[base] = s[r];
        #pragma unroll
        for (int p = 0; p < 5; p++) {
            float lo, hi; unpack2(accp[r][p], lo, hi);
            g_pacc[(size_t)base * HD + 2 * p]     = lo;
            g_pacc[(size_t)base * HD + 2 * p + 1] = hi;
        }
    }
}

// ---------------- kernel 4: combine + out_proj + LN + MLP + LN + head --------
__global__ __launch_bounds__(256) void epi_kernel(
    const float* __restrict__ opw, const float* __restrict__ opb,
    const float* __restrict__ f1w, const float* __restrict__ f1b,
    const float* __restrict__ f2w, const float* __restrict__ f2b,
    const float* __restrict__ lng, const float* __restrict__ lnb,
    const float* __restrict__ ow,  const float* __restrict__ ob,
    float* __restrict__ out)
{
    int warp = (blockIdx.x * blockDim.x + threadIdx.x) >> 5;
    int lane = threadIdx.x & 31;
    bool act = lane < E;
    int li = act ? lane : 0;
    int hh = li / HD, dd = li - hh * HD;

    // combine split-softmax partials
    float num = 0.0f, den = 0.0f;
    #pragma unroll
    for (int ksp = 0; ksp < KSPLIT; ksp++) {
        int base = (hh * KSPLIT + ksp) * BB + warp;
        num += g_pacc[(size_t)base * HD + dd];
        den += g_psum[base];
    }
    float ctx = __fdividef(num, den);

    // out_proj
    float ao = __ldg(opb + li);
    #pragma unroll
    for (int j = 0; j < E; j++) {
        float cj = __shfl_sync(0xffffffffu, ctx, j);
        ao = fmaf(__ldg(opw + li * E + j), cj, ao);
    }
    float r1 = ao + g_hn[(size_t)warp * E + li];

    // LN1
    float lg = __ldg(lng + li), lb = __ldg(lnb + li);
    float mu = warp_sum(act ? r1 : 0.0f) * (1.0f / E);
    float dv = act ? (r1 - mu) : 0.0f;
    float var = warp_sum(dv * dv) * (1.0f / E);
    float x1 = fmaf(dv * rsqrtf(var + 1e-5f), lg, lb);
    if (!act) x1 = 0.0f;

    // fc1 + exact GELU
    float y = __ldg(f1b + li);
    #pragma unroll
    for (int j = 0; j < E; j++) {
        float xj = __shfl_sync(0xffffffffu, x1, j);
        y = fmaf(__ldg(f1w + li * E + j), xj, y);
    }
    float gy = 0.5f * y * (1.0f + erff(y * 0.7071067811865475f));

    // fc2
    float z = __ldg(f2b + li);
    #pragma unroll
    for (int j = 0; j < E; j++) {
        float gj = __shfl_sync(0xffffffffu, gy, j);
        z = fmaf(__ldg(f2w + li * E + j), gj, z);
    }
    float r2 = x1 + z;

    // LN2
    float mu2 = warp_sum(act ? r2 : 0.0f) * (1.0f / E);
    float dv2 = act ? (r2 - mu2) : 0.0f;
    float var2 = warp_sum(dv2 * dv2) * (1.0f / E);
    float x2 = fmaf(dv2 * rsqrtf(var2 + 1e-5f), lg, lb);
    if (!act) x2 = 0.0f;

    // final head [E -> 3]
    float o0 = __ldg(ob + 0), o1 = __ldg(ob + 1), o2 = __ldg(ob + 2);
    #pragma unroll
    for (int j = 0; j < E; j++) {
        float xj = __shfl_sync(0xffffffffu, x2, j);
        o0 = fmaf(__ldg(ow + 0 * E + j), xj, o0);
        o1 = fmaf(__ldg(ow + 1 * E + j), xj, o1);
        o2 = fmaf(__ldg(ow + 2 * E + j), xj, o2);
    }
    if (lane == 0) {
        out[(size_t)warp * 3 + 0] = o0;
        out[(size_t)warp * 3 + 1] = o1;
        out[(size_t)warp * 3 + 2] = o2;
    }
}

// ---------------- launch ------------------------------------------------------
extern "C" void kernel_launch(void* const* d_in, const int* in_sizes, int n_in,
                              void* d_out, int out_size)
{
    const float* input = (const float*)d_in[0];   // [4096,512,5]
    const float* w_ih  = (const float*)d_in[1];   // [120,5]
    const float* w_hh  = (const float*)d_in[2];   // [120,30]
    const float* b_ih  = (const float*)d_in[3];   // [120]
    const float* b_hh  = (const float*)d_in[4];   // [120]
    const float* ipw   = (const float*)d_in[5];   // [90,30]
    const float* ipb   = (const float*)d_in[6];   // [90]
    const float* opw   = (const float*)d_in[7];   // [30,30]
    const float* opb   = (const float*)d_in[8];   // [30]
    const float* f1w   = (const float*)d_in[9];   // [30,30]
    const float* f1b   = (const float*)d_in[10];  // [30]
    const float* f2w   = (const float*)d_in[11];  // [30,30]
    const float* f2b   = (const float*)d_in[12];  // [30]
    const float* lng   = (const float*)d_in[13];  // [30]
    const float* lnb   = (const float*)d_in[14];  // [30]
    const float* ow    = (const float*)d_in[15];  // [3,30]
    const float* ob    = (const float*)d_in[16];  // [3]
    float* out = (float*)d_out;

    lstm_kernel<<<BB / 4, 128>>>(input, w_ih, w_hh, b_ih, b_hh);
    qkv_kernel<<<BB / 8, 256>>>(ipw, ipb);
    attn_kernel<<<dim3(BB / (128 * RQ), KSPLIT, NH), 128>>>();
    epi_kernel<<<BB / 8, 256>>>(opw, opb, f1w, f1b, f2w, f2b, lng, lnb, ow, ob, out);
}

// round 4
// speedup vs baseline: 1.9116x; 1.2406x over previous
#include <cuda_runtime.h>
#include <cstdint>

#define BB 4096
#define TT 512
#define IND 5
#define E 30
#define NH 3
#define HD 10
#define KSPLIT 8
#define KTILE 512   // 4096 / KSPLIT
#define RQ 4        // q rows per thread in attention
#define CH 16       // LSTM steps per prefetched x chunk (CH*IND = 80 floats)

typedef unsigned long long u64;

// ---------------- scratch (device globals; no allocations allowed) ----------
__device__ float g_hn[BB * E];
__device__ float g_cn[BB * E];
__device__ float g_q[BB * E];
__device__ float g_k[BB * E];
__device__ float g_v[BB * E];
__device__ float g_psum[NH * KSPLIT * BB];
__device__ float g_pacc[NH * KSPLIT * BB * HD];

// ---------------- f32x2 helpers ----------------------------------------------
__device__ __forceinline__ u64 pack2(float lo, float hi) {
    u64 r; asm("mov.b64 %0, {%1, %2};" : "=l"(r) : "f"(lo), "f"(hi)); return r;
}
__device__ __forceinline__ u64 bcast2(float v) {
    u64 r; asm("mov.b64 %0, {%1, %1};" : "=l"(r) : "f"(v)); return r;
}
__device__ __forceinline__ void unpack2(u64 p, float& lo, float& hi) {
    asm("mov.b64 {%0, %1}, %2;" : "=f"(lo), "=f"(hi) : "l"(p));
}
__device__ __forceinline__ u64 ffma2(u64 a, u64 b, u64 c) {
    u64 d; asm("fma.rn.f32x2 %0, %1, %2, %3;" : "=l"(d) : "l"(a), "l"(b), "l"(c));
    return d;
}

// ---------------- activation helpers -----------------------------------------
__device__ __forceinline__ float tanh_fast(float x) {
    float y; asm("tanh.approx.f32 %0, %1;" : "=f"(y) : "f"(x)); return y;
}
__device__ __forceinline__ float sig_fast(float x) {
    return fmaf(0.5f, tanh_fast(0.5f * x), 0.5f);
}
__device__ __forceinline__ float warp_sum(float v) {
    #pragma unroll
    for (int o = 16; o > 0; o >>= 1) v += __shfl_xor_sync(0xffffffffu, v, o);
    return v;
}

// ---------------- kernel 1: LSTM --------------------------------------------
// j-packed f32x2 recurrent weights (FFMA2), h staged via smem LDS.64 pairs,
// x streamed through smem in CH-step chunks prefetched 2 chunks ahead,
// activations on the single-MUFU tanh.approx path.
__global__ __launch_bounds__(128, 2) void lstm_kernel(
    const float* __restrict__ input, const float* __restrict__ w_ih,
    const float* __restrict__ w_hh, const float* __restrict__ b_ih,
    const float* __restrict__ b_hh)
{
    __shared__ __align__(16) float hbuf[4][2][32];        // [warp][buf][lane]
    __shared__ __align__(16) float xs[4][2][CH * 6];      // padded 6 floats/step

    int wl   = threadIdx.x >> 5;
    int warp = blockIdx.x * 4 + wl;
    int lane = threadIdx.x & 31;
    bool act = lane < E;
    int li = act ? lane : 0;

    // packed recurrent weights: whh2[g][p] = (W[g*E+li][2p], W[g*E+li][2p+1])
    u64 whh2[4][15];
    #pragma unroll
    for (int g = 0; g < 4; g++) {
        const float* wr = w_hh + (g * E + li) * E;
        #pragma unroll
        for (int p = 0; p < 15; p++)
            whh2[g][p] = pack2(__ldg(wr + 2 * p), __ldg(wr + 2 * p + 1));
    }
    u64 wx01[4], wx23[4];
    float wx4[4], bias[4];
    #pragma unroll
    for (int g = 0; g < 4; g++) {
        const float* wr = w_ih + (g * E + li) * IND;
        wx01[g] = pack2(__ldg(wr + 0), __ldg(wr + 1));
        wx23[g] = pack2(__ldg(wr + 2), __ldg(wr + 3));
        wx4[g]  = __ldg(wr + 4);
        bias[g] = __ldg(b_ih + g * E + li) + __ldg(b_hh + g * E + li);
    }

    const float* xbase = input + (size_t)warp * TT * IND;

    // cooperative x staging: lanes 0..19 each load one float4 per chunk
    float4 pf = make_float4(0.f, 0.f, 0.f, 0.f);
    bool ldr = lane < 20;
    int s0 = 0, c0 = 0;            // step/comp for this lane's 4 floats
    if (ldr) { int g0 = lane * 4; s0 = g0 / 5; c0 = g0 - s0 * 5; }

    auto unpack_chunk = [&](float* xd, float4 v) {
        if (ldr) {
            int s = s0, cc = c0;
            float vv[4] = {v.x, v.y, v.z, v.w};
            #pragma unroll
            for (int j = 0; j < 4; j++) {
                xd[s * 6 + cc] = vv[j];
                if (++cc == 5) { cc = 0; s++; }
            }
        }
    };

    // chunk 0: load + unpack
    if (ldr) pf = *(const float4*)(xbase + lane * 4);
    unpack_chunk(xs[wl][0], pf);
    __syncwarp();
    // kick prefetch of chunk 1
    if (ldr) pf = *(const float4*)(xbase + CH * IND + lane * 4);

    float h = 0.0f, c = 0.0f;
    const u64 zero2 = pack2(0.0f, 0.0f);

    for (int ch = 0; ch < TT / CH; ch++) {
        const float* xc = xs[wl][ch & 1];
        #pragma unroll
        for (int s = 0; s < CH; s++) {
            // stage h into smem (double-buffered)
            float* hb = hbuf[wl][s & 1];
            hb[lane] = h;
            __syncwarp();
            const u64* hv = (const u64*)hb;
            u64 hp[15];
            #pragma unroll
            for (int p = 0; p < 15; p++) hp[p] = hv[p];

            u64 x01 = *(const u64*)(xc + s * 6);
            u64 x23 = *(const u64*)(xc + s * 6 + 2);
            float x4 = xc[s * 6 + 4];

            float a[4];
            #pragma unroll
            for (int g = 0; g < 4; g++) {
                u64 a2 = ffma2(wx01[g], x01, zero2);
                a2 = ffma2(wx23[g], x23, a2);
                #pragma unroll
                for (int p = 0; p < 15; p++) a2 = ffma2(whh2[g][p], hp[p], a2);
                float lo, hi; unpack2(a2, lo, hi);
                a[g] = fmaf(wx4[g], x4, bias[g]) + lo + hi;
            }

            float ig = sig_fast(a[0]);
            float fg = sig_fast(a[1]);
            float gg = tanh_fast(a[2]);
            float og = sig_fast(a[3]);
            c = fmaf(fg, c, ig * gg);
            h = og * tanh_fast(c);
        }
        // stage chunk ch+1 (already in flight) and prefetch ch+2
        if (ch + 1 < TT / CH) {
            unpack_chunk(xs[wl][(ch + 1) & 1], pf);
            __syncwarp();
            if (ch + 2 < TT / CH && ldr)
                pf = *(const float4*)(xbase + (ch + 2) * CH * IND + lane * 4);
        }
    }

    if (act) {
        g_hn[(size_t)warp * E + lane] = h;
        g_cn[(size_t)warp * E + lane] = c;
    }
}

// ---------------- kernel 2: QKV projections (warp per row) --------------------
__global__ __launch_bounds__(256) void qkv_kernel(
    const float* __restrict__ ipw, const float* __restrict__ ipb)
{
    int warp = (blockIdx.x * blockDim.x + threadIdx.x) >> 5;
    int lane = threadIdx.x & 31;
    bool act = lane < E;
    int li = act ? lane : 0;

    float h = g_hn[(size_t)warp * E + li];
    float c = g_cn[(size_t)warp * E + li];
    float aq = __ldg(ipb + 0 * E + li);
    float ak = __ldg(ipb + 1 * E + li);
    float av = __ldg(ipb + 2 * E + li);
    #pragma unroll
    for (int j = 0; j < E; j++) {
        float hj = __shfl_sync(0xffffffffu, h, j);
        float cj = __shfl_sync(0xffffffffu, c, j);
        aq = fmaf(__ldg(ipw + (0 * E + li) * E + j), hj, aq);
        ak = fmaf(__ldg(ipw + (1 * E + li) * E + j), cj, ak);
        av = fmaf(__ldg(ipw + (2 * E + li) * E + j), cj, av);
    }
    if (act) {
        g_q[(size_t)warp * E + lane] = aq;
        g_k[(size_t)warp * E + lane] = ak;
        g_v[(size_t)warp * E + lane] = av;
    }
}

// ---------------- kernel 3: attention partials (flash-style, no-max) ----------
__global__ __launch_bounds__(128) void attn_kernel()
{
    __shared__ u64 ks2[KTILE * 5];
    __shared__ u64 vs2[KTILE * 5];
    int h   = blockIdx.z;
    int ksp = blockIdx.y;
    int qc  = blockIdx.x;
    int tid = threadIdx.x;
    int k0  = ksp * KTILE;

    for (int i = tid; i < KTILE * 5; i += 128) {
        int m = i / 5, p = i - m * 5;
        const float2* kp = (const float2*)(g_k + (size_t)(k0 + m) * E + h * HD) + p;
        const float2* vp = (const float2*)(g_v + (size_t)(k0 + m) * E + h * HD) + p;
        float2 kv = *kp; float2 vv = *vp;
        ks2[i] = pack2(kv.x, kv.y);
        vs2[i] = pack2(vv.x, vv.y);
    }
    __syncthreads();

    int q0 = qc * (128 * RQ) + tid * RQ;

    u64 qp[RQ][5], accp[RQ][5];
    float s[RQ];
    #pragma unroll
    for (int r = 0; r < RQ; r++) {
        s[r] = 0.0f;
        #pragma unroll
        for (int p = 0; p < 5; p++) {
            float2 t = *((const float2*)(g_q + (size_t)(q0 + r) * E + h * HD) + p);
            qp[r][p] = pack2(t.x * 0.3162277660168379f, t.y * 0.3162277660168379f);
            accp[r][p] = pack2(0.0f, 0.0f);
        }
    }

    for (int m = 0; m < KTILE; m++) {
        u64 kk[5], vv[5];
        #pragma unroll
        for (int p = 0; p < 5; p++) { kk[p] = ks2[m * 5 + p]; vv[p] = vs2[m * 5 + p]; }
        #pragma unroll
        for (int r = 0; r < RQ; r++) {
            u64 d2 = pack2(0.0f, 0.0f);
            #pragma unroll
            for (int p = 0; p < 5; p++) d2 = ffma2(qp[r][p], kk[p], d2);
            float lo, hi; unpack2(d2, lo, hi);
            float pr = __expf(lo + hi);
            s[r] += pr;
            u64 p2 = bcast2(pr);
            #pragma unroll
            for (int p = 0; p < 5; p++) accp[r][p] = ffma2(p2, vv[p], accp[r][p]);
        }
    }

    #pragma unroll
    for (int r = 0; r < RQ; r++) {
        int base = (h * KSPLIT + ksp) * BB + (q0 + r);
        g_psum[base] = s[r];
        #pragma unroll
        for (int p = 0; p < 5; p++) {
            float lo, hi; unpack2(accp[r][p], lo, hi);
            g_pacc[(size_t)base * HD + 2 * p]     = lo;
            g_pacc[(size_t)base * HD + 2 * p + 1] = hi;
        }
    }
}

// ---------------- kernel 4: combine + out_proj + LN + MLP + LN + head --------
__global__ __launch_bounds__(256) void epi_kernel(
    const float* __restrict__ opw, const float* __restrict__ opb,
    const float* __restrict__ f1w, const float* __restrict__ f1b,
    const float* __restrict__ f2w, const float* __restrict__ f2b,
    const float* __restrict__ lng, const float* __restrict__ lnb,
    const float* __restrict__ ow,  const float* __restrict__ ob,
    float* __restrict__ out)
{
    int warp = (blockIdx.x * blockDim.x + threadIdx.x) >> 5;
    int lane = threadIdx.x & 31;
    bool act = lane < E;
    int li = act ? lane : 0;
    int hh = li / HD, dd = li - hh * HD;

    // combine split-softmax partials
    float num = 0.0f, den = 0.0f;
    #pragma unroll
    for (int ksp = 0; ksp < KSPLIT; ksp++) {
        int base = (hh * KSPLIT + ksp) * BB + warp;
        num += g_pacc[(size_t)base * HD + dd];
        den += g_psum[base];
    }
    float ctx = __fdividef(num, den);

    // out_proj
    float ao = __ldg(opb + li);
    #pragma unroll
    for (int j = 0; j < E; j++) {
        float cj = __shfl_sync(0xffffffffu, ctx, j);
        ao = fmaf(__ldg(opw + li * E + j), cj, ao);
    }
    float r1 = ao + g_hn[(size_t)warp * E + li];

    // LN1
    float lg = __ldg(lng + li), lb = __ldg(lnb + li);
    float mu = warp_sum(act ? r1 : 0.0f) * (1.0f / E);
    float dv = act ? (r1 - mu) : 0.0f;
    float var = warp_sum(dv * dv) * (1.0f / E);
    float x1 = fmaf(dv * rsqrtf(var + 1e-5f), lg, lb);
    if (!act) x1 = 0.0f;

    // fc1 + exact GELU
    float y = __ldg(f1b + li);
    #pragma unroll
    for (int j = 0; j < E; j++) {
        float xj = __shfl_sync(0xffffffffu, x1, j);
        y = fmaf(__ldg(f1w + li * E + j), xj, y);
    }
    float gy = 0.5f * y * (1.0f + erff(y * 0.7071067811865475f));

    // fc2
    float z = __ldg(f2b + li);
    #pragma unroll
    for (int j = 0; j < E; j++) {
        float gj = __shfl_sync(0xffffffffu, gy, j);
        z = fmaf(__ldg(f2w + li * E + j), gj, z);
    }
    float r2 = x1 + z;

    // LN2
    float mu2 = warp_sum(act ? r2 : 0.0f) * (1.0f / E);
    float dv2 = act ? (r2 - mu2) : 0.0f;
    float var2 = warp_sum(dv2 * dv2) * (1.0f / E);
    float x2 = fmaf(dv2 * rsqrtf(var2 + 1e-5f), lg, lb);
    if (!act) x2 = 0.0f;

    // final head [E -> 3]
    float o0 = __ldg(ob + 0), o1 = __ldg(ob + 1), o2 = __ldg(ob + 2);
    #pragma unroll
    for (int j = 0; j < E; j++) {
        float xj = __shfl_sync(0xffffffffu, x2, j);
        o0 = fmaf(__ldg(ow + 0 * E + j), xj, o0);
        o1 = fmaf(__ldg(ow + 1 * E + j), xj, o1);
        o2 = fmaf(__ldg(ow + 2 * E + j), xj, o2);
    }
    if (lane == 0) {
        out[(size_t)warp * 3 + 0] = o0;
        out[(size_t)warp * 3 + 1] = o1;
        out[(size_t)warp * 3 + 2] = o2;
    }
}

// ---------------- launch ------------------------------------------------------
extern "C" void kernel_launch(void* const* d_in, const int* in_sizes, int n_in,
                              void* d_out, int out_size)
{
    const float* input = (const float*)d_in[0];   // [4096,512,5]
    const float* w_ih  = (const float*)d_in[1];   // [120,5]
    const float* w_hh  = (const float*)d_in[2];   // [120,30]
    const float* b_ih  = (const float*)d_in[3];   // [120]
    const float* b_hh  = (const float*)d_in[4];   // [120]
    const float* ipw   = (const float*)d_in[5];   // [90,30]
    const float* ipb   = (const float*)d_in[6];   // [90]
    const float* opw   = (const float*)d_in[7];   // [30,30]
    const float* opb   = (const float*)d_in[8];   // [30]
    const float* f1w   = (const float*)d_in[9];   // [30,30]
    const float* f1b   = (const float*)d_in[10];  // [30]
    const float* f2w   = (const float*)d_in[11];  // [30,30]
    const float* f2b   = (const float*)d_in[12];  // [30]
    const float* lng   = (const float*)d_in[13];  // [30]
    const float* lnb   = (const float*)d_in[14];  // [30]
    const float* ow    = (const float*)d_in[15];  // [3,30]
    const float* ob    = (const float*)d_in[16];  // [3]
    float* out = (float*)d_out;

    lstm_kernel<<<BB / 4, 128>>>(input, w_ih, w_hh, b_ih, b_hh);
    qkv_kernel<<<BB / 8, 256>>>(ipw, ipb);
    attn_kernel<<<dim3(BB / (128 * RQ), KSPLIT, NH), 128>>>();
    epi_kernel<<<BB / 8, 256>>>(opw, opb, f1w, f1b, f2w, f2b, lng, lnb, ow, ob, out);
}